// round 12
// baseline (speedup 1.0000x reference)
#include <cuda_runtime.h>
#include <math.h>

#define NN 50000
#define EE 800000
#define FF 100
#define HH 64
#define CC 40

// ---------------- scratch (device globals; referenced ONLY from device code) -
__device__ int   g_is64;                 // 1 if edge_index buffer is int64
__device__ int   g_deg[NN];
__device__ int   g_cur[NN];
__device__ int   g_off[NN + 1];
__device__ float g_dinv[NN];
__device__ int   g_col[EE];
__device__ float g_norm[EE];

__device__ float g_Tx1 [(size_t)NN * FF];
__device__ float g_Tx2 [(size_t)NN * FF];
__device__ float g_h   [(size_t)NN * HH];
__device__ float g_hTx1[(size_t)NN * HH];
__device__ float g_hTx2[(size_t)NN * HH];
__device__ float g_logits[(size_t)NN * CC];

// ---------------- dtype probe ------------------------------------------------
// If ei holds int64 node ids (< 50000), the high 32-bit word of every element
// is 0. Sample 256 words: int32 data (random ids in [0,50000)) being all-zero
// at those positions is impossible in practice.
__global__ void probe_kernel(const int* __restrict__ ei32) {
    int allzero = 1;
    for (int k = 0; k < 256; k++)
        if (ei32[2 * k + 1] != 0) { allzero = 0; break; }
    g_is64 = allzero;
}

__device__ __forceinline__ int load_idx(const int* ei32, long long pos) {
    // pos = logical element index in [0, 2E)
    return g_is64 ? ei32[2 * pos] : ei32[pos];
}

// ---------------- CSR build --------------------------------------------------
__global__ void zero_kernel() {
    int i = blockIdx.x * blockDim.x + threadIdx.x;
    if (i < NN) { g_deg[i] = 0; g_cur[i] = 0; }
}

__global__ void hist_kernel(const int* __restrict__ ei32) {
    int e = blockIdx.x * blockDim.x + threadIdx.x;
    if (e < EE) {
        int r = load_idx(ei32, e);
        if (r >= 0 && r < NN) atomicAdd(&g_deg[r], 1);
    }
}

// single-block exclusive scan of degrees + dinv
__global__ void scan_kernel() {
    __shared__ int sh[1024];
    int tid = threadIdx.x;
    int running = 0;
    for (int base = 0; base < NN; base += 1024) {
        int i = base + tid;
        int v = (i < NN) ? g_deg[i] : 0;
        sh[tid] = v;
        __syncthreads();
        #pragma unroll
        for (int off = 1; off < 1024; off <<= 1) {
            int t = (tid >= off) ? sh[tid - off] : 0;
            __syncthreads();
            sh[tid] += t;
            __syncthreads();
        }
        if (i < NN) {
            g_off[i]  = running + sh[tid] - v;        // exclusive prefix
            g_dinv[i] = (v > 0) ? rsqrtf((float)v) : 0.0f;
        }
        running += sh[1023];
        __syncthreads();
    }
    if (tid == 0) g_off[NN] = running;
}

__global__ void build_kernel(const int* __restrict__ ei32) {
    int e = blockIdx.x * blockDim.x + threadIdx.x;
    if (e < EE) {
        int r = load_idx(ei32, e);
        int c = load_idx(ei32, (long long)EE + e);
        if (r >= 0 && r < NN && c >= 0 && c < NN) {
            int p = g_off[r] + atomicAdd(&g_cur[r], 1);
            g_col[p]  = c;
            g_norm[p] = -g_dinv[r] * g_dinv[c];
        }
    }
}

// ---------------- SpMV -------------------------------------------------------
// MODE 0: g_Tx1  = L @ x                (src = xin,   W = FF)
// MODE 1: g_Tx2  = 2 L @ g_Tx1  - x    (other = xin, W = FF)
// MODE 2: g_hTx1 = L @ g_h              (W = HH)
// MODE 3: g_hTx2 = 2 L @ g_hTx1 - g_h  (W = HH)
template <int W, int MODE>
__global__ void spmv_kernel(const float* __restrict__ xin) {
    const float* src   = (MODE == 0) ? xin
                       : (MODE == 1) ? (const float*)g_Tx1
                       : (MODE == 2) ? (const float*)g_h
                                     : (const float*)g_hTx1;
    const float* other = (MODE == 1) ? xin
                       : (MODE == 3) ? (const float*)g_h
                                     : nullptr;
    float* dst         = (MODE == 0) ? g_Tx1
                       : (MODE == 1) ? g_Tx2
                       : (MODE == 2) ? g_hTx1
                                     : g_hTx2;
    const float alpha  = (MODE == 1 || MODE == 3) ? 2.0f : 1.0f;

    int warp = (blockIdx.x * blockDim.x + threadIdx.x) >> 5;
    int lane = threadIdx.x & 31;
    if (warp >= NN) return;

    constexpr int U = (W + 31) / 32;
    float acc[U];
    #pragma unroll
    for (int u = 0; u < U; u++) acc[u] = 0.0f;

    int s = g_off[warp];
    int e = g_off[warp + 1];
    for (int j = s; j < e; j++) {
        int   c = g_col[j];
        float w = g_norm[j];
        const float* sr = src + (size_t)c * W;
        #pragma unroll
        for (int u = 0; u < U; u++) {
            int f = lane + 32 * u;
            if (f < W) acc[u] += w * sr[f];
        }
    }

    float* dr = dst + (size_t)warp * W;
    #pragma unroll
    for (int u = 0; u < U; u++) {
        int f = lane + 32 * u;
        if (f < W) {
            float v = alpha * acc[u];
            if (MODE == 1 || MODE == 3) v -= other[(size_t)warp * W + f];
            dr[f] = v;
        }
    }
}

// ---------------- fused 3-way GEMM: out = act([A0|A1|A2] @ W + bias) ---------
// L1: srcs = {xin, g_Tx1, g_Tx2}, out = g_h,        FW=FF, NC=HH, RELU
// !L1: srcs = {g_h, g_hTx1, g_hTx2}, out = g_logits, FW=HH, NC=CC
template <int FW, int NC, int KC, bool L1>
__global__ void gemm3_kernel(const float* __restrict__ xin,
                             const float* __restrict__ Wt,
                             const float* __restrict__ bias) {
    constexpr int BM = 64;
    constexpr int KTOT = 3 * FW;
    __shared__ __align__(16) float As[KC][BM];
    __shared__ __align__(16) float Ws[KC][NC];

    const int tx  = threadIdx.x;          // 0 .. NC/4-1
    const int ty  = threadIdx.y;          // 0 .. 15
    const int tid = ty * blockDim.x + tx;
    const int nth = blockDim.x * blockDim.y;
    const int r0  = blockIdx.x * BM;

    const float* srcs[3];
    srcs[0] = L1 ? xin : (const float*)g_h;
    srcs[1] = L1 ? (const float*)g_Tx1 : (const float*)g_hTx1;
    srcs[2] = L1 ? (const float*)g_Tx2 : (const float*)g_hTx2;
    float* out = L1 ? g_h : g_logits;

    float acc[4][4];
    #pragma unroll
    for (int i = 0; i < 4; i++)
        #pragma unroll
        for (int j = 0; j < 4; j++) acc[i][j] = 0.0f;

    for (int k0 = 0; k0 < KTOT; k0 += KC) {
        // stage A chunk (transposed into As[k][m])
        for (int l = tid; l < BM * KC; l += nth) {
            int row = l / KC;
            int kk  = l - row * KC;
            int kg  = k0 + kk;
            int sidx = kg / FW;
            int f    = kg - sidx * FW;
            int r    = r0 + row;
            As[kk][row] = (r < NN) ? srcs[sidx][(size_t)r * FW + f] : 0.0f;
        }
        // stage W chunk
        for (int l = tid; l < KC * NC; l += nth) {
            int kk = l / NC;
            int j  = l - kk * NC;
            Ws[kk][j] = Wt[(size_t)(k0 + kk) * NC + j];
        }
        __syncthreads();

        #pragma unroll
        for (int kk = 0; kk < KC; kk++) {
            float4 a4 = *(const float4*)&As[kk][ty * 4];
            float4 b4 = *(const float4*)&Ws[kk][tx * 4];
            float av[4] = {a4.x, a4.y, a4.z, a4.w};
            float bv[4] = {b4.x, b4.y, b4.z, b4.w};
            #pragma unroll
            for (int i = 0; i < 4; i++)
                #pragma unroll
                for (int j = 0; j < 4; j++)
                    acc[i][j] += av[i] * bv[j];
        }
        __syncthreads();
    }

    #pragma unroll
    for (int i = 0; i < 4; i++) {
        int r = r0 + ty * 4 + i;
        if (r < NN) {
            #pragma unroll
            for (int j = 0; j < 4; j++) {
                float v = acc[i][j] + bias[tx * 4 + j];
                if (L1) v = fmaxf(v, 0.0f);          // relu only on layer 1
                out[(size_t)r * NC + tx * 4 + j] = v;
            }
        }
    }
}

// ---------------- log_softmax (warp per row, C = 40) -------------------------
__global__ void lsm_kernel(float* __restrict__ out) {
    int warp = (blockIdx.x * blockDim.x + threadIdx.x) >> 5;
    int lane = threadIdx.x & 31;
    if (warp >= NN) return;
    const float* r = g_logits + (size_t)warp * CC;

    float v0 = (lane < CC) ? r[lane] : -INFINITY;
    float v1 = (lane + 32 < CC) ? r[lane + 32] : -INFINITY;

    float m = fmaxf(v0, v1);
    #pragma unroll
    for (int o = 16; o; o >>= 1) m = fmaxf(m, __shfl_xor_sync(0xffffffffu, m, o));

    float s = 0.0f;
    if (lane < CC)      s += expf(v0 - m);
    if (lane + 32 < CC) s += expf(v1 - m);
    #pragma unroll
    for (int o = 16; o; o >>= 1) s += __shfl_xor_sync(0xffffffffu, s, o);

    float lse = m + logf(s);
    float* orow = out + (size_t)warp * CC;
    if (lane < CC)      orow[lane]      = v0 - lse;
    if (lane + 32 < CC) orow[lane + 32] = v1 - lse;
}

// ---------------- launch -----------------------------------------------------
extern "C" void kernel_launch(void* const* d_in, const int* in_sizes, int n_in,
                              void* d_out, int out_size) {
    const float* x  = (const float*)d_in[0];
    const int*   ei = (const int*)d_in[1];        // raw words; dtype probed on device
    const float* W1 = (const float*)d_in[2];      // [3,100,64] == [300][64]
    const float* b1 = (const float*)d_in[3];
    const float* W2 = (const float*)d_in[4];      // [3,64,40]  == [192][40]
    const float* b2 = (const float*)d_in[5];
    float*       out = (float*)d_out;

    // dtype probe + CSR build
    probe_kernel<<<1, 1>>>(ei);
    zero_kernel<<<(NN + 255) / 256, 256>>>();
    hist_kernel<<<(EE + 255) / 256, 256>>>(ei);
    scan_kernel<<<1, 1024>>>();
    build_kernel<<<(EE + 255) / 256, 256>>>(ei);

    const int SPMV_BLK = 256;                          // 8 warps / block
    const int spmv_grid = (NN * 32 + SPMV_BLK - 1) / SPMV_BLK;

    // Layer 1: Tx1 = L x ; Tx2 = 2 L Tx1 - x
    spmv_kernel<FF, 0><<<spmv_grid, SPMV_BLK>>>(x);
    spmv_kernel<FF, 1><<<spmv_grid, SPMV_BLK>>>(x);

    // h = relu([x|Tx1|Tx2] @ W1 + b1)
    {
        dim3 blk(HH / 4, 16);
        int grid = (NN + 63) / 64;
        gemm3_kernel<FF, HH, 20, true><<<grid, blk>>>(x, W1, b1);
    }

    // Layer 2: hTx1 = L h ; hTx2 = 2 L hTx1 - h
    spmv_kernel<HH, 2><<<spmv_grid, SPMV_BLK>>>(nullptr);
    spmv_kernel<HH, 3><<<spmv_grid, SPMV_BLK>>>(nullptr);

    // logits = [h|hTx1|hTx2] @ W2 + b2
    {
        dim3 blk(CC / 4, 16);
        int grid = (NN + 63) / 64;
        gemm3_kernel<HH, CC, 16, false><<<grid, blk>>>(nullptr, W2, b2);
    }

    // out = log_softmax(logits)
    lsm_kernel<<<spmv_grid, SPMV_BLK>>>(out);
}